// round 9
// baseline (speedup 1.0000x reference)
#include <cuda_runtime.h>
#include <cuda_fp16.h>

#define NN 100000
#define EMAX 1600000
#define EPS 1e-5f
#define NB ((NN + 1023) >> 10)     // 98 scan blocks
#define GSTRIDE 88                 // smem row stride (uints): conflict-free LDS.64/STS.128

typedef unsigned int uint;

// ---- scratch (device globals) ----
// interleaved fp16 layout: per row 128 k-values = 8 groups x 8 uints (half2 each),
// group order [k01,k89,k23,k10-11,k45,k12-13,k67,k14-15]
__device__ __align__(256) uint   g_xh [NN * 64];          // x, fp16 interleaved
__device__ __align__(256) uint   g_ag1[NN * 64];          // mean-agg(x), fp16 interleaved
__device__ __align__(256) __half g_hx [(NN + 128) * 128]; // x@(W1r*gp)^T partial, fp16 plain (padded)
__device__ __align__(256) __half g_y2l[NN * 64];          // h@W2l^T, fp16 plain
__device__ __align__(256) float  g_y2r[NN * 64];          // h@W2r^T, fp32 plain
__device__ int g_cnt_i[NN];
__device__ int g_off[NN + 1];
__device__ int g_cur[NN];
__device__ int g_bsum[NB];
__device__ int g_ssrc[EMAX];

// ---- helpers ----
__device__ __forceinline__ uint h2u(float lo, float hi) {
    __half2 h = __floats2half2_rn(lo, hi);
    return *(uint*)&h;
}
__device__ __forceinline__ void mma16(float* d, const uint* a, const uint* b) {
    asm("mma.sync.aligned.m16n8k16.row.col.f32.f16.f16.f32 "
        "{%0,%1,%2,%3}, {%4,%5,%6,%7}, {%8,%9}, {%0,%1,%2,%3};"
        : "+f"(d[0]), "+f"(d[1]), "+f"(d[2]), "+f"(d[3])
        : "r"(a[0]), "r"(a[1]), "r"(a[2]), "r"(a[3]), "r"(b[0]), "r"(b[1]));
}

// ===========================================================================
__global__ void zerocnt_kernel() {
    int i = blockIdx.x * blockDim.x + threadIdx.x;
    if (i < NN) g_cnt_i[i] = 0;
}

// convert x -> interleaved fp16
__global__ void convx_kernel(const float* __restrict__ x) {
    int u = blockIdx.x * 256 + threadIdx.x;
    if (u >= NN * 8) return;
    int row = u >> 3, g = u & 7;
    const float4* p = (const float4*)(x + row * 128 + g * 16);
    float4 a = __ldg(p);
    float4 b = __ldg(p + 1);
    float4 c = __ldg(p + 2);
    float4 d = __ldg(p + 3);
    uint4 o0 = make_uint4(h2u(a.x, a.y), h2u(c.x, c.y), h2u(a.z, a.w), h2u(c.z, c.w));
    uint4 o1 = make_uint4(h2u(b.x, b.y), h2u(d.x, d.y), h2u(b.z, b.w), h2u(d.z, d.w));
    uint4* q = (uint4*)(g_xh + row * 64 + g * 8);
    q[0] = o0; q[1] = o1;
}

// ===========================================================================
// CSR build
// ===========================================================================
__global__ void hist_kernel(const int* __restrict__ dst, int E) {
    int e = blockIdx.x * blockDim.x + threadIdx.x;
    if (e < E) atomicAdd(&g_cnt_i[dst[e]], 1);
}

__global__ void scan1_kernel() {
    __shared__ int sm[1024];
    int tid = threadIdx.x;
    int i = blockIdx.x * 1024 + tid;
    int v = (i < NN) ? g_cnt_i[i] : 0;
    sm[tid] = v;
    __syncthreads();
    for (int off = 1; off < 1024; off <<= 1) {
        int t = (tid >= off) ? sm[tid - off] : 0;
        __syncthreads();
        sm[tid] += t;
        __syncthreads();
    }
    if (i < NN) g_off[i] = sm[tid] - v;
    if (tid == 1023) g_bsum[blockIdx.x] = sm[1023];
}

__global__ void scan23_kernel(int E) {
    __shared__ int sm[128];
    int tid = threadIdx.x;
    if (tid < 128) sm[tid] = (tid < NB) ? g_bsum[tid] : 0;
    __syncthreads();
    for (int off = 1; off < 128; off <<= 1) {
        int t = (tid < 128 && tid >= off) ? sm[tid - off] : 0;
        __syncthreads();
        if (tid < 128) sm[tid] += t;
        __syncthreads();
    }
    int i = blockIdx.x * blockDim.x + tid;
    if (i < NN) {
        int b = i >> 10;
        int o = g_off[i] + (b ? sm[b - 1] : 0);
        g_off[i] = o;
        g_cur[i] = o;
    }
    if (i == 0) g_off[NN] = E;
}

__global__ void fill_kernel(const int* __restrict__ src,
                            const int* __restrict__ dst, int E) {
    int e = blockIdx.x * blockDim.x + threadIdx.x;
    if (e >= E) return;
    int p = atomicAdd(&g_cur[dst[e]], 1);
    g_ssrc[p] = src[e];
}

// ===========================================================================
// agg1: warp per dst, gather interleaved fp16 x rows, write MEAN (interleaved)
// ===========================================================================
__global__ void __launch_bounds__(256) agg1_kernel() {
    int w = (blockIdx.x * 256 + threadIdx.x) >> 5;
    if (w >= NN) return;
    int lane = threadIdx.x & 31;
    int beg = g_off[w], end = g_off[w + 1];
    float a0 = 0.f, a1 = 0.f, a2 = 0.f, a3 = 0.f;
    const uint2* xh = (const uint2*)g_xh;
    int e = beg;
    for (; e + 4 <= end; e += 4) {
        uint2 v0 = __ldg(xh + (long long)__ldg(g_ssrc + e)     * 32 + lane);
        uint2 v1 = __ldg(xh + (long long)__ldg(g_ssrc + e + 1) * 32 + lane);
        uint2 v2 = __ldg(xh + (long long)__ldg(g_ssrc + e + 2) * 32 + lane);
        uint2 v3 = __ldg(xh + (long long)__ldg(g_ssrc + e + 3) * 32 + lane);
        float2 f;
        f = __half22float2(*(__half2*)&v0.x); a0 += f.x; a1 += f.y;
        f = __half22float2(*(__half2*)&v0.y); a2 += f.x; a3 += f.y;
        f = __half22float2(*(__half2*)&v1.x); a0 += f.x; a1 += f.y;
        f = __half22float2(*(__half2*)&v1.y); a2 += f.x; a3 += f.y;
        f = __half22float2(*(__half2*)&v2.x); a0 += f.x; a1 += f.y;
        f = __half22float2(*(__half2*)&v2.y); a2 += f.x; a3 += f.y;
        f = __half22float2(*(__half2*)&v3.x); a0 += f.x; a1 += f.y;
        f = __half22float2(*(__half2*)&v3.y); a2 += f.x; a3 += f.y;
    }
    for (; e < end; e++) {
        uint2 v0 = __ldg(xh + (long long)__ldg(g_ssrc + e) * 32 + lane);
        float2 f;
        f = __half22float2(*(__half2*)&v0.x); a0 += f.x; a1 += f.y;
        f = __half22float2(*(__half2*)&v0.y); a2 += f.x; a3 += f.y;
    }
    float inv = 1.f / (float)max(end - beg, 1);
    uint2 o = make_uint2(h2u(a0 * inv, a1 * inv), h2u(a2 * inv, a3 * inv));
    ((uint2*)g_ag1)[w * 32 + lane] = o;
}

// ===========================================================================
// agg2 + epilogue fused: out[d] = mean_agg(y2l fp16) + b2l + y2r[d]
// ===========================================================================
__global__ void __launch_bounds__(256) agg2_kernel(const float* __restrict__ b2l,
                                                   float* __restrict__ out) {
    int w = (blockIdx.x * 256 + threadIdx.x) >> 5;
    if (w >= NN) return;
    int lane = threadIdx.x & 31;
    int beg = g_off[w], end = g_off[w + 1];
    float ax = 0.f, ay = 0.f;
    const uint* yl = (const uint*)g_y2l;
    int e = beg;
    for (; e + 4 <= end; e += 4) {
        uint v0 = __ldg(yl + (long long)__ldg(g_ssrc + e)     * 32 + lane);
        uint v1 = __ldg(yl + (long long)__ldg(g_ssrc + e + 1) * 32 + lane);
        uint v2 = __ldg(yl + (long long)__ldg(g_ssrc + e + 2) * 32 + lane);
        uint v3 = __ldg(yl + (long long)__ldg(g_ssrc + e + 3) * 32 + lane);
        float2 f;
        f = __half22float2(*(__half2*)&v0); ax += f.x; ay += f.y;
        f = __half22float2(*(__half2*)&v1); ax += f.x; ay += f.y;
        f = __half22float2(*(__half2*)&v2); ax += f.x; ay += f.y;
        f = __half22float2(*(__half2*)&v3); ax += f.x; ay += f.y;
    }
    for (; e < end; e++) {
        uint v0 = __ldg(yl + (long long)__ldg(g_ssrc + e) * 32 + lane);
        float2 f = __half22float2(*(__half2*)&v0);
        ax += f.x; ay += f.y;
    }
    float inv = 1.f / (float)max(end - beg, 1);
    int j = lane * 2;
    float2 yr = *(const float2*)(g_y2r + (long long)w * 64 + j);
    float2 o = make_float2(ax * inv + __ldg(b2l + j)     + yr.x,
                           ay * inv + __ldg(b2l + j + 1) + yr.y);
    *(float2*)(out + (long long)w * 64 + j) = o;
}

// ===========================================================================
// fp16 HMMA GEMMs. Block tile 128x128, 8 warps, warp tile 32x64, k-chunk 128.
// ===========================================================================
#define TILE_U (128 * GSTRIDE)
#define GEMMX_SMEM ((2 * TILE_U + 128) * 4)
#define GEMMA_SMEM ((2 * TILE_U + 256) * 4)

__device__ __forceinline__ void copy_tile(uint* S, const uint* __restrict__ src,
                                          int g0, int tid) {
    #pragma unroll
    for (int it = 0; it < 8; it++) {
        int u = it * 256 + tid;
        int r = u >> 4, j = u & 15;
        int grow = g0 + r;
        uint4 v = make_uint4(0u, 0u, 0u, 0u);
        if (grow < NN) v = __ldg((const uint4*)(src + grow * 64) + j);
        *(uint4*)(S + r * GSTRIDE + j * 4) = v;
    }
}

__device__ __forceinline__ void convw_tile(uint* S, const float* __restrict__ W0,
                                           const float* gp, int tid) {
    #pragma unroll
    for (int it = 0; it < 8; it++) {
        int u = it * 256 + tid;
        int n = u >> 4, g = (u >> 1) & 7, h = u & 1;
        const float* p = W0 + n * 128 + g * 16 + 4 * h;
        float4 A = __ldg((const float4*)p);
        float4 B = __ldg((const float4*)(p + 8));
        float s = gp ? gp[n] : 1.f;
        uint4 o = make_uint4(h2u(A.x * s, A.y * s), h2u(B.x * s, B.y * s),
                             h2u(A.z * s, A.w * s), h2u(B.z * s, B.w * s));
        *(uint4*)(S + n * GSTRIDE + g * 8 + 4 * h) = o;
    }
}

struct FAcc { float a[2][8][4]; };

__device__ __forceinline__ void acc_zero(FAcc& acc) {
    #pragma unroll
    for (int i = 0; i < 2; i++)
        #pragma unroll
        for (int j = 0; j < 8; j++)
            #pragma unroll
            for (int q = 0; q < 4; q++) acc.a[i][j][q] = 0.f;
}

__device__ __forceinline__ void mainloop_h(const uint* As, const uint* Ws,
                                           int warpM, int warpN, int fr, int cc,
                                           FAcc& acc) {
    const uint* Ab = As + (warpM * 32 + fr) * GSTRIDE + 2 * cc;
    const uint* Bb = Ws + (warpN * 64 + fr) * GSTRIDE + 2 * cc;
    #pragma unroll
    for (int g = 0; g < 8; g++) {
        uint a[2][4];
        #pragma unroll
        for (int mt = 0; mt < 2; mt++) {
            uint2 p0 = *(const uint2*)(Ab + (mt * 16) * GSTRIDE + g * 8);
            uint2 p1 = *(const uint2*)(Ab + (mt * 16 + 8) * GSTRIDE + g * 8);
            a[mt][0] = p0.x; a[mt][1] = p1.x; a[mt][2] = p0.y; a[mt][3] = p1.y;
        }
        #pragma unroll
        for (int nt = 0; nt < 8; nt++) {
            uint2 q = *(const uint2*)(Bb + (nt * 8) * GSTRIDE + g * 8);
            uint b[2] = {q.x, q.y};
            mma16(acc.a[0][nt], a[0], b);
            mma16(acc.a[1][nt], a[1], b);
        }
    }
}

// gemmX: g_hx = x @ (W1r*gp)^T  (plain fp16; runs concurrently with CSR build)
__global__ void __launch_bounds__(256, 2) gemmX_kernel(
    const float* __restrict__ W1r,
    const float* __restrict__ gamma, const float* __restrict__ rvar)
{
    extern __shared__ uint smu[];
    uint* As = smu;
    uint* Ws = smu + TILE_U;
    float* gp = (float*)(smu + 2 * TILE_U);

    int tid = threadIdx.x;
    int g0 = blockIdx.x * 128;
    if (tid < 128) gp[tid] = gamma[tid] * rsqrtf(rvar[tid] + EPS);
    __syncthreads();

    convw_tile(Ws, W1r, gp, tid);
    copy_tile(As, g_xh, g0, tid);
    __syncthreads();

    int lane = tid & 31, wid = tid >> 5;
    int warpM = wid >> 1, warpN = wid & 1;
    int fr = lane >> 2, cc = lane & 3;

    FAcc acc;
    acc_zero(acc);
    mainloop_h(As, Ws, warpM, warpN, fr, cc, acc);

    #pragma unroll
    for (int mt = 0; mt < 2; mt++) {
        int r0 = g0 + warpM * 32 + mt * 16 + fr;
        #pragma unroll
        for (int nt = 0; nt < 8; nt++) {
            int col = warpN * 64 + nt * 8 + 2 * cc;
            if (r0 < NN)
                *(__half2*)(g_hx + (long long)r0 * 128 + col) =
                    __floats2half2_rn(acc.a[mt][nt][0], acc.a[mt][nt][1]);
            if (r0 + 8 < NN)
                *(__half2*)(g_hx + (long long)(r0 + 8) * 128 + col) =
                    __floats2half2_rn(acc.a[mt][nt][2], acc.a[mt][nt][3]);
        }
    }
}

// gemmA: h = ReLU(agg1@(W1l*gp)^T + g_hx + bias) kept in smem, then
//        y2l = h@W2l^T (fp16), y2r = h@W2r^T (fp32)
__global__ void __launch_bounds__(256, 2) gemmA_kernel(
    const float* __restrict__ W1l, const float* __restrict__ b1l,
    const float* __restrict__ gamma, const float* __restrict__ beta,
    const float* __restrict__ rmean, const float* __restrict__ rvar,
    const float* __restrict__ W2l, const float* __restrict__ W2r)
{
    extern __shared__ uint smu[];
    uint* As = smu;
    uint* Ws = smu + TILE_U;
    float* gp   = (float*)(smu + 2 * TILE_U);
    float* bias = gp + 128;

    int tid = threadIdx.x;
    int g0 = blockIdx.x * 128;

    if (tid < 128) {
        float g = gamma[tid] * rsqrtf(rvar[tid] + EPS);
        gp[tid] = g;
        bias[tid] = (b1l[tid] - rmean[tid]) * g + beta[tid];
    }
    __syncthreads();

    convw_tile(Ws, W1l, gp, tid);
    copy_tile(As, g_ag1, g0, tid);
    __syncthreads();

    int lane = tid & 31, wid = tid >> 5;
    int warpM = wid >> 1, warpN = wid & 1;
    int fr = lane >> 2, cc = lane & 3;

    FAcc acc;
    acc_zero(acc);
    mainloop_h(As, Ws, warpM, warpN, fr, cc, acc);
    __syncthreads();   // all reads of As/Ws done

    // epilogue1: h -> As (interleaved fp16), plus W2 -> Ws
    #pragma unroll
    for (int mt = 0; mt < 2; mt++) {
        int rl = warpM * 32 + mt * 16 + fr;      // local row
        int r0 = g0 + rl;
        #pragma unroll
        for (int nt = 0; nt < 8; nt++) {
            int col = warpN * 64 + nt * 8 + 2 * cc;
            int t4 = (col & 15) >> 1;
            int j = (t4 < 4) ? 2 * t4 : 2 * (t4 - 4) + 1;
            int uidx = (col >> 4) * 8 + j;
            float b0 = bias[col], b1v = bias[col + 1];
            float2 p0 = make_float2(0.f, 0.f), p1 = make_float2(0.f, 0.f);
            if (r0 < NN)
                p0 = __half22float2(*(const __half2*)(g_hx + (long long)r0 * 128 + col));
            if (r0 + 8 < NN)
                p1 = __half22float2(*(const __half2*)(g_hx + (long long)(r0 + 8) * 128 + col));
            As[rl * GSTRIDE + uidx] =
                h2u(fmaxf(acc.a[mt][nt][0] + p0.x + b0, 0.f),
                    fmaxf(acc.a[mt][nt][1] + p0.y + b1v, 0.f));
            As[(rl + 8) * GSTRIDE + uidx] =
                h2u(fmaxf(acc.a[mt][nt][2] + p1.x + b0, 0.f),
                    fmaxf(acc.a[mt][nt][3] + p1.y + b1v, 0.f));
        }
    }
    // W2 tile: n 0..63 -> W2l, 64..127 -> W2r
    #pragma unroll
    for (int it = 0; it < 8; it++) {
        int u = it * 256 + tid;
        int n = u >> 4, g = (u >> 1) & 7, h = u & 1;
        const float* Wsrc = (n < 64) ? (W2l + n * 128) : (W2r + (n - 64) * 128);
        const float* p = Wsrc + g * 16 + 4 * h;
        float4 A = __ldg((const float4*)p);
        float4 B = __ldg((const float4*)(p + 8));
        uint4 o = make_uint4(h2u(A.x, A.y), h2u(B.x, B.y),
                             h2u(A.z, A.w), h2u(B.z, B.w));
        *(uint4*)(Ws + n * GSTRIDE + g * 8 + 4 * h) = o;
    }
    __syncthreads();

    acc_zero(acc);
    mainloop_h(As, Ws, warpM, warpN, fr, cc, acc);

    // epilogue2: warpN==0 -> y2l fp16 plain; warpN==1 -> y2r fp32 plain
    #pragma unroll
    for (int mt = 0; mt < 2; mt++) {
        int r0 = g0 + warpM * 32 + mt * 16 + fr;
        #pragma unroll
        for (int nt = 0; nt < 8; nt++) {
            int colL = nt * 8 + 2 * cc;
            if (warpN == 0) {
                if (r0 < NN)
                    *(__half2*)(g_y2l + (long long)r0 * 64 + colL) =
                        __floats2half2_rn(acc.a[mt][nt][0], acc.a[mt][nt][1]);
                if (r0 + 8 < NN)
                    *(__half2*)(g_y2l + (long long)(r0 + 8) * 64 + colL) =
                        __floats2half2_rn(acc.a[mt][nt][2], acc.a[mt][nt][3]);
            } else {
                if (r0 < NN)
                    *(float2*)(g_y2r + (long long)r0 * 64 + colL) =
                        make_float2(acc.a[mt][nt][0], acc.a[mt][nt][1]);
                if (r0 + 8 < NN)
                    *(float2*)(g_y2r + (long long)(r0 + 8) * 64 + colL) =
                        make_float2(acc.a[mt][nt][2], acc.a[mt][nt][3]);
            }
        }
    }
}

// ===========================================================================
extern "C" void kernel_launch(void* const* d_in, const int* in_sizes, int n_in,
                              void* d_out, int out_size) {
    const float* x     = (const float*)d_in[0];
    const int*   ei    = (const int*)d_in[1];     // int32 (JAX x64 disabled)
    const float* W1l   = (const float*)d_in[2];
    const float* b1l   = (const float*)d_in[3];
    const float* W1r   = (const float*)d_in[4];
    const float* gamma = (const float*)d_in[5];
    const float* beta  = (const float*)d_in[6];
    const float* rmean = (const float*)d_in[7];
    const float* rvar  = (const float*)d_in[8];
    const float* W2l   = (const float*)d_in[9];
    const float* b2l   = (const float*)d_in[10];
    const float* W2r   = (const float*)d_in[11];
    float* out = (float*)d_out;

    int E = in_sizes[1] / 2;
    if (E > EMAX) E = EMAX;
    const int* src = ei;
    const int* dst = ei + E;

    cudaFuncSetAttribute(gemmX_kernel, cudaFuncAttributeMaxDynamicSharedMemorySize, GEMMX_SMEM);
    cudaFuncSetAttribute(gemmA_kernel, cudaFuncAttributeMaxDynamicSharedMemorySize, GEMMA_SMEM);

    int nBlk  = (NN + 255) / 256;         // 391
    int eBlk  = (E + 255) / 256;          // 6250
    int wBlk  = (NN * 32 + 255) / 256;    // 12500
    int gBlk  = (NN + 127) / 128;         // 782
    int cBlk  = (NN * 8 + 255) / 256;     // 3125

    // side stream + events (created per call; not destroyed — capture-safe,
    // only the few eager/capture invocations ever run this host code)
    cudaStream_t s2;
    cudaStreamCreateWithFlags(&s2, cudaStreamNonBlocking);
    cudaEvent_t e0, e1, e2;
    cudaEventCreateWithFlags(&e0, cudaEventDisableTiming);
    cudaEventCreateWithFlags(&e1, cudaEventDisableTiming);
    cudaEventCreateWithFlags(&e2, cudaEventDisableTiming);

    // fork stream B off the capture stream
    cudaEventRecord(e0, 0);
    cudaStreamWaitEvent(s2, e0, 0);

    // stream B: convert x, then x@(W1r*gp)^T — independent of the graph build
    convx_kernel<<<cBlk, 256, 0, s2>>>(x);
    cudaEventRecord(e1, s2);
    gemmX_kernel<<<gBlk, 256, GEMMX_SMEM, s2>>>(W1r, gamma, rvar);
    cudaEventRecord(e2, s2);

    // stream A (capture stream): CSR build
    zerocnt_kernel<<<nBlk, 256>>>();
    hist_kernel<<<eBlk, 256>>>(dst, E);
    scan1_kernel<<<NB, 1024>>>();
    scan23_kernel<<<nBlk, 256>>>(E);
    fill_kernel<<<eBlk, 256>>>(src, dst, E);

    cudaStreamWaitEvent(0, e1, 0);        // agg1 needs g_xh
    agg1_kernel<<<wBlk, 256>>>();

    cudaStreamWaitEvent(0, e2, 0);        // gemmA needs g_hx
    gemmA_kernel<<<gBlk, 256, GEMMA_SMEM>>>(W1l, b1l, gamma, beta, rmean, rvar, W2l, W2r);
    agg2_kernel<<<wBlk, 256>>>(b2l, out);
}